// round 7
// baseline (speedup 1.0000x reference)
#include <cuda_runtime.h>
#include <math.h>

#define NN 50000
#define NE 800000
#define NF 256
#define NH 128
#define NC 40
#define NCP 64   // padded row stride for g_g2 (256B-aligned rows)

// ---- scratch (static device globals; module-load allocation, legal) ----
__device__ int   g_deg[NN];
__device__ int   g_cur[NN];
__device__ int   g_offs[NN + 1];
__device__ int   g_csr[NE];
__device__ float g_dinv[NN];
__device__ float g_g1[(size_t)NN * NH];    // dinv[i] * (x @ W1)[i]
__device__ float g_a1[(size_t)NN * NH];    // relu(aggregated layer1 + b1)
__device__ float g_g2[(size_t)NN * NCP];   // dinv[i] * (a1 @ W2)[i], padded rows

// ---------------------------------------------------------------
__global__ void k_zero() {
    int i = blockIdx.x * blockDim.x + threadIdx.x;
    if (i < NN) { g_deg[i] = 0; g_cur[i] = 0; }
}

__global__ void k_hist(const int* __restrict__ dst) {
    int i = blockIdx.x * blockDim.x + threadIdx.x;
    if (i < NE) atomicAdd(&g_deg[dst[i]], 1);
}

// exclusive prefix sum over g_deg (1 block), also computes dinv = rsqrt(indeg+1)
__global__ void k_scan() {
    __shared__ int sh[1024];
    __shared__ int carry;
    int tid = threadIdx.x;
    if (tid == 0) { carry = 0; g_offs[0] = 0; }
    __syncthreads();
    for (int base = 0; base < NN; base += 1024) {
        int i = base + tid;
        int v = (i < NN) ? g_deg[i] : 0;
        if (i < NN) g_dinv[i] = rsqrtf((float)(v + 1));  // +1 = self loop
        sh[tid] = v;
        __syncthreads();
        for (int off = 1; off < 1024; off <<= 1) {
            int t = 0;
            if (tid >= off) t = sh[tid - off];
            __syncthreads();
            if (tid >= off) sh[tid] += t;
            __syncthreads();
        }
        if (i < NN) g_offs[i + 1] = carry + sh[tid];
        __syncthreads();
        if (tid == 0) carry += sh[1023];
        __syncthreads();
    }
}

__global__ void k_scatter(const int* __restrict__ src, const int* __restrict__ dst) {
    int i = blockIdx.x * blockDim.x + threadIdx.x;
    if (i < NE) {
        int d = dst[i];
        int pos = g_offs[d] + atomicAdd(&g_cur[d], 1);
        g_csr[pos] = src[i];
    }
}

// ---------------------------------------------------------------
// GEMM1: g1 = dinv[row] * (X[NN,256] @ W1[256,128])
// BM=128, BN=128, BK=32, 256 threads, 8x8 register tile per thread.
__global__ void __launch_bounds__(256) k_gemm1(const float* __restrict__ X,
                                               const float* __restrict__ W) {
    __shared__ float xs[128][36];   // padded, float4-aligned rows
    __shared__ float ws[32][128];
    int tid  = threadIdx.x;
    int trow = tid >> 4;            // 0..15 -> rows trow*8..+7
    int tcol = tid & 15;            // 0..15 -> cols tcol*8..+7
    int rowbase = blockIdx.x * 128;

    float acc[8][8];
#pragma unroll
    for (int i = 0; i < 8; i++)
#pragma unroll
        for (int j = 0; j < 8; j++) acc[i][j] = 0.f;

    for (int kt = 0; kt < NF; kt += 32) {
        // X tile: 128x32 = 1024 float4
#pragma unroll
        for (int l = 0; l < 4; l++) {
            int idx = tid + l * 256;            // 0..1023
            int r = idx >> 3, k4 = idx & 7;
            int grow = rowbase + r;
            float4 v = make_float4(0.f, 0.f, 0.f, 0.f);
            if (grow < NN) v = *(const float4*)&X[(size_t)grow * NF + kt + k4 * 4];
            *(float4*)&xs[r][k4 * 4] = v;
        }
        // W tile: 32x128 = 1024 float4
#pragma unroll
        for (int l = 0; l < 4; l++) {
            int idx = tid + l * 256;
            int k = idx >> 5, n4 = idx & 31;
            *(float4*)&ws[k][n4 * 4] = *(const float4*)&W[(size_t)(kt + k) * NH + n4 * 4];
        }
        __syncthreads();

#pragma unroll 8
        for (int kk = 0; kk < 32; kk++) {
            float a[8];
#pragma unroll
            for (int i = 0; i < 8; i++) a[i] = xs[trow * 8 + i][kk];
            float4 b0 = *(float4*)&ws[kk][tcol * 8];
            float4 b1 = *(float4*)&ws[kk][tcol * 8 + 4];
#pragma unroll
            for (int i = 0; i < 8; i++) {
                acc[i][0] += a[i] * b0.x;
                acc[i][1] += a[i] * b0.y;
                acc[i][2] += a[i] * b0.z;
                acc[i][3] += a[i] * b0.w;
                acc[i][4] += a[i] * b1.x;
                acc[i][5] += a[i] * b1.y;
                acc[i][6] += a[i] * b1.z;
                acc[i][7] += a[i] * b1.w;
            }
        }
        __syncthreads();
    }

#pragma unroll
    for (int i = 0; i < 8; i++) {
        int row = rowbase + trow * 8 + i;
        if (row < NN) {
            float di = g_dinv[row];
#pragma unroll
            for (int j = 0; j < 8; j += 4) {
                float4 o;
                o.x = acc[i][j + 0] * di;
                o.y = acc[i][j + 1] * di;
                o.z = acc[i][j + 2] * di;
                o.w = acc[i][j + 3] * di;
                *(float4*)&g_g1[(size_t)row * NH + tcol * 8 + j] = o;
            }
        }
    }
}

// ---------------------------------------------------------------
// agg1: one warp per node.  a1 = relu(dinv[d]*(sum_{e:dst=d} g1[src] + g1[d]) + b1)
__global__ void __launch_bounds__(256) k_agg1(const float* __restrict__ b1) {
    int warp = (blockIdx.x * blockDim.x + threadIdx.x) >> 5;
    int lane = threadIdx.x & 31;
    if (warp >= NN) return;
    int node = warp;

    float4 acc = *(const float4*)&g_g1[(size_t)node * NH + lane * 4];  // self loop
    int s0 = g_offs[node], s1 = g_offs[node + 1];
    for (int base = s0; base < s1; base += 32) {
        int e = base + lane;
        int sidx = (e < s1) ? __ldg(&g_csr[e]) : 0;
        int cnt = min(32, s1 - base);
#pragma unroll 1
        for (int j = 0; j < cnt; j++) {
            int sj = __shfl_sync(0xffffffffu, sidx, j);
            float4 v = __ldg((const float4*)&g_g1[(size_t)sj * NH + lane * 4]);
            acc.x += v.x; acc.y += v.y; acc.z += v.z; acc.w += v.w;
        }
    }
    float di = g_dinv[node];
    float4 bb = *(const float4*)&b1[lane * 4];
    float4 o;
    o.x = fmaxf(di * acc.x + bb.x, 0.f);
    o.y = fmaxf(di * acc.y + bb.y, 0.f);
    o.z = fmaxf(di * acc.z + bb.z, 0.f);
    o.w = fmaxf(di * acc.w + bb.w, 0.f);
    *(float4*)&g_a1[(size_t)node * NH + lane * 4] = o;
}

// ---------------------------------------------------------------
// GEMM2: g2 = dinv[row] * (a1[NN,128] @ W2[128,40]), rows padded to NCP.
// BM=48 rows/block, 320 threads: col = tid%40, rowg = tid/40 (6 rows each).
__global__ void __launch_bounds__(320) k_gemm2(const float* __restrict__ W2) {
    __shared__ float As[48][128];    // natural row-major
    __shared__ float Wt[40][132];    // transposed W2, padded
    int tid = threadIdx.x;
    int rowbase = blockIdx.x * 48;

    // load A tile: 48x128 = 1536 float4
    for (int idx = tid; idx < 1536; idx += 320) {
        int r = idx >> 5, k4 = idx & 31;
        int grow = rowbase + r;
        float4 v = make_float4(0.f, 0.f, 0.f, 0.f);
        if (grow < NN) v = *(const float4*)&g_a1[(size_t)grow * NH + k4 * 4];
        *(float4*)&As[r][k4 * 4] = v;
    }
    // load W2 transposed: 128x40 floats
    for (int idx = tid; idx < NH * NC; idx += 320) {
        int k = idx / NC, c = idx % NC;
        Wt[c][k] = W2[idx];
    }
    __syncthreads();

    int col  = tid % 40;
    int rowg = tid / 40;            // 0..7
    float acc[6];
#pragma unroll
    for (int r = 0; r < 6; r++) acc[r] = 0.f;

#pragma unroll 4
    for (int k = 0; k < NH; k += 4) {
        float4 w4 = *(float4*)&Wt[col][k];
#pragma unroll
        for (int r = 0; r < 6; r++) {
            float4 a4 = *(float4*)&As[rowg * 6 + r][k];
            acc[r] += a4.x * w4.x + a4.y * w4.y + a4.z * w4.z + a4.w * w4.w;
        }
    }
#pragma unroll
    for (int r = 0; r < 6; r++) {
        int row = rowbase + rowg * 6 + r;
        if (row < NN)
            g_g2[(size_t)row * NCP + col] = acc[r] * g_dinv[row];
    }
}

// ---------------------------------------------------------------
// agg2 + bias + log_softmax, one warp per node. 40 feats: lane and lane+32 (<8).
__global__ void __launch_bounds__(256) k_agg2(const float* __restrict__ b2,
                                              float* __restrict__ out) {
    int warp = (blockIdx.x * blockDim.x + threadIdx.x) >> 5;
    int lane = threadIdx.x & 31;
    if (warp >= NN) return;
    int node = warp;
    size_t rb = (size_t)node * NCP;

    float a0 = g_g2[rb + lane];                                  // self loop
    float a1v = (lane < 8) ? g_g2[rb + 32 + lane] : 0.f;
    int s0 = g_offs[node], s1 = g_offs[node + 1];
    for (int base = s0; base < s1; base += 32) {
        int e = base + lane;
        int sidx = (e < s1) ? __ldg(&g_csr[e]) : 0;
        int cnt = min(32, s1 - base);
#pragma unroll 1
        for (int j = 0; j < cnt; j++) {
            int sj = __shfl_sync(0xffffffffu, sidx, j);
            size_t sb = (size_t)sj * NCP;
            a0 += __ldg(&g_g2[sb + lane]);
            if (lane < 8) a1v += __ldg(&g_g2[sb + 32 + lane]);
        }
    }
    float di = g_dinv[node];
    float v0 = di * a0 + b2[lane];
    float v1 = (lane < 8) ? (di * a1v + b2[32 + lane]) : -INFINITY;

    float m = fmaxf(v0, v1);
#pragma unroll
    for (int o = 16; o > 0; o >>= 1) m = fmaxf(m, __shfl_xor_sync(0xffffffffu, m, o));
    float s = expf(v0 - m) + ((lane < 8) ? expf(v1 - m) : 0.f);
#pragma unroll
    for (int o = 16; o > 0; o >>= 1) s += __shfl_xor_sync(0xffffffffu, s, o);
    float lse = m + logf(s);

    size_t ob = (size_t)node * NC;
    out[ob + lane] = v0 - lse;
    if (lane < 8) out[ob + 32 + lane] = v1 - lse;
}

// ---------------------------------------------------------------
extern "C" void kernel_launch(void* const* d_in, const int* in_sizes, int n_in,
                              void* d_out, int out_size) {
    const float* x  = (const float*)d_in[0];
    const int*   ei = (const int*)d_in[1];
    const float* W1 = (const float*)d_in[2];
    const float* b1 = (const float*)d_in[3];
    const float* W2 = (const float*)d_in[4];
    const float* b2 = (const float*)d_in[5];
    float* out = (float*)d_out;
    const int* src = ei;
    const int* dst = ei + NE;

    k_zero<<<(NN + 255) / 256, 256>>>();
    k_hist<<<(NE + 255) / 256, 256>>>(dst);
    k_scan<<<1, 1024>>>();
    k_scatter<<<(NE + 255) / 256, 256>>>(src, dst);
    k_gemm1<<<(NN + 127) / 128, 256>>>(x, W1);
    k_agg1<<<(NN + 7) / 8, 256>>>(b1);
    k_gemm2<<<(NN + 47) / 48, 320>>>(W2);
    k_agg2<<<(NN + 7) / 8, 256>>>(b2, out);
}